// round 16
// baseline (speedup 1.0000x reference)
#include <cuda_runtime.h>
#include <cuda_fp16.h>
#include <cstdint>

// Problem shape (fixed by the reference)
constexpr int BD = 4096;   // batch rows
constexpr int DD = 1024;   // model dim
constexpr int HD = 2048;   // hidden dim
constexpr int ED = 8;      // experts

// GEMM tiling: 128x128x32 CTA tile, 64x32 warp tile, 8 warps, 2 CTAs/SM.
// 5-stage cp.async ring, prefetch distance 4, wait_group<3>. (plateau-optimal)
constexpr int BM = 128, BN = 128, BK = 32;
constexpr int STAGES = 5;
constexpr int ASTR = BK + 8;              // 40 halves/row
constexpr int BSTR = BN + 8;              // 136 halves/row
constexpr int A_STAGE = BM * ASTR;        // 5120 halves
constexpr int B_STAGE = BK * BSTR;        // 4352 halves
constexpr size_t SMEM_BYTES = (size_t)STAGES * (A_STAGE + B_STAGE) * sizeof(__half); // 94720

// Convert ranges in float8 (32B) units
constexpr int N8_X    = (BD * DD) / 8;         // 524288
constexpr int N8_W1E  = (DD * HD) / 8;         // 262144 per expert
constexpr int NC_W1E  = 64;                    // W1 convert CTAs per expert (e>0)
constexpr int N8_PER_W1CVT = N8_W1E / NC_W1E;  // 4096
constexpr int NC_W2E  = 64;                    // W2 convert CTAs per expert
constexpr int N8_PER_W2CVT = N8_W1E / NC_W2E;  // 4096 (same size per expert)

// Fused-kernel block layout.
// Per-expert block: [e>0: 64 W1-cvt] + 64 groups of 9 (1 W2-cvt + 8 GEMM1) = 576/640
constexpr int EBLK0 = 576;                     // expert 0 block
constexpr int EBLKN = NC_W1E + 576;            // experts 1..7 block (640)
constexpr int REGION1 = EBLK0 + 7 * EBLKN;     // 5056
constexpr int NT2 = (DD / BN) * (BD / BM) * ED; // 2048 GEMM2 tiles
constexpr int FUSED_GRID = REGION1 + NT2;      // 7104

// Scratch (allocation-free: __device__ globals)
__device__ __align__(256) __half g_xh [(size_t)BD * DD];
__device__ __align__(256) __half g_w1h[(size_t)ED * DD * HD];
__device__ __align__(256) __half g_w2h[(size_t)ED * HD * DD];
__device__ __align__(256) __half g_h  [(size_t)ED * BD * HD];

// Sync: [e*32+ty] = h row-block counters (256), [256+e] = W1 cvt (8),
//       [264+e] = W2 cvt per-expert (8)
constexpr int SYNC_N = ED * 32 + ED + ED;      // 272
__device__ int g_sync[SYNC_N];

// ---------------------------------------------------------------- convert helpers
__device__ __forceinline__ void cvt8(const float4* s, uint4* d, int j) {
    float4 v0 = s[2 * j];
    float4 v1 = s[2 * j + 1];
    __half2 h0 = __floats2half2_rn(v0.x, v0.y);
    __half2 h1 = __floats2half2_rn(v0.z, v0.w);
    __half2 h2 = __floats2half2_rn(v1.x, v1.y);
    __half2 h3 = __floats2half2_rn(v1.z, v1.w);
    uint4 o;
    o.x = *reinterpret_cast<uint32_t*>(&h0);
    o.y = *reinterpret_cast<uint32_t*>(&h1);
    o.z = *reinterpret_cast<uint32_t*>(&h2);
    o.w = *reinterpret_cast<uint32_t*>(&h3);
    d[j] = o;
}

// Pre-kernel: convert x + W1 expert 0 (needed at fused-kernel start), full chip
constexpr int N8_PRE = N8_X + N8_W1E;
__global__ void cvt_pre(const float* __restrict__ x, const float* __restrict__ W1,
                        __half* __restrict__ xh, __half* __restrict__ w1h) {
    for (int i = blockIdx.x * blockDim.x + threadIdx.x; i < N8_PRE;
         i += gridDim.x * blockDim.x) {
        if (i < N8_X) cvt8((const float4*)x, (uint4*)xh, i);
        else          cvt8((const float4*)W1, (uint4*)w1h, i - N8_X);
    }
}

// ---------------------------------------------------------------- PTX utils
__device__ __forceinline__ void cp16(uint32_t saddr, const void* g) {
    asm volatile("cp.async.cg.shared.global [%0], [%1], 16;\n" :: "r"(saddr), "l"(g));
}
__device__ __forceinline__ void cp_commit() { asm volatile("cp.async.commit_group;\n"); }
template<int N> __device__ __forceinline__ void cp_wait() {
    asm volatile("cp.async.wait_group %0;\n" :: "n"(N));
}
__device__ __forceinline__ void ldsm4(uint32_t* r, uint32_t saddr) {
    asm volatile("ldmatrix.sync.aligned.m8n8.x4.shared.b16 {%0,%1,%2,%3}, [%4];\n"
        : "=r"(r[0]), "=r"(r[1]), "=r"(r[2]), "=r"(r[3]) : "r"(saddr));
}
__device__ __forceinline__ void ldsm4t(uint32_t* r, uint32_t saddr) {
    asm volatile("ldmatrix.sync.aligned.m8n8.x4.trans.shared.b16 {%0,%1,%2,%3}, [%4];\n"
        : "=r"(r[0]), "=r"(r[1]), "=r"(r[2]), "=r"(r[3]) : "r"(saddr));
}
__device__ __forceinline__ void mma16816(float* c, const uint32_t* a, uint32_t b0, uint32_t b1) {
    asm volatile("mma.sync.aligned.m16n8k16.row.col.f32.f16.f16.f32 "
        "{%0,%1,%2,%3}, {%4,%5,%6,%7}, {%8,%9}, {%0,%1,%2,%3};\n"
        : "+f"(c[0]), "+f"(c[1]), "+f"(c[2]), "+f"(c[3])
        : "r"(a[0]), "r"(a[1]), "r"(a[2]), "r"(a[3]), "r"(b0), "r"(b1));
}

// ---------------------------------------------------------------- fused kernel
__global__ __launch_bounds__(256, 2)
void fused_kernel(const __half* __restrict__ xh, const __half* __restrict__ w1h,
                  __half* __restrict__ hbuf,
                  const float* __restrict__ W1, const float* __restrict__ W2,
                  __half* __restrict__ w1hw, __half* __restrict__ w2h,
                  const float* __restrict__ b1, const float* __restrict__ b2,
                  float* __restrict__ out)
{
    extern __shared__ __align__(16) __half smem[];
    const int bid = blockIdx.x;
    const int tid = threadIdx.x;

    bool g1 = false;
    int e, ty, tx, N, K;
    const __half *Az, *Bz;
    const float* biz;

    if (bid < REGION1) {
        // Decode expert block
        int eb, r;
        if (bid < EBLK0) { eb = 0; r = bid; }
        else { int b = bid - EBLK0; eb = 1 + b / EBLKN; r = b % EBLKN; }

        if (eb > 0 && r < NC_W1E) {
            // ---------------- W1[eb] convert CTA ----------------
            const float4* s = (const float4*)W1;
            uint4* d = (uint4*)w1hw;
            int base = eb * N8_W1E + r * N8_PER_W1CVT;
            #pragma unroll 4
            for (int i = tid; i < N8_PER_W1CVT; i += 256)
                cvt8(s, d, base + i);
            __syncthreads();
            if (tid == 0) { __threadfence(); atomicAdd(&g_sync[256 + eb], 1); }
            return;
        }
        int r2 = (eb > 0) ? r - NC_W1E : r;   // 0..575
        const int grp = r2 / 9;
        const int sub = r2 - grp * 9;
        if (sub == 0) {
            // ---------------- W2[eb] convert CTA (interleaved) ----------------
            const float4* s = (const float4*)W2;
            uint4* d = (uint4*)w2h;
            int base = (eb * NC_W2E + grp) * N8_PER_W2CVT;   // expert eb's slice
            #pragma unroll 4
            for (int i = tid; i < N8_PER_W2CVT; i += 256)
                cvt8(s, d, base + i);
            __syncthreads();
            if (tid == 0) { __threadfence(); atomicAdd(&g_sync[264 + eb], 1); }
            return;
        }
        // ---------------- GEMM1 tile ----------------
        g1 = true;
        e = eb;
        int t = grp * 8 + (sub - 1);          // t = tx + 16*ty within expert
        tx = t & 15; ty = t >> 4;
        N = HD; K = DD;
        Az = xh;
        Bz = w1h + (size_t)e * DD * HD;
        biz = b1 + (size_t)e * HD;
        if (e > 0) {
            if (tid == 0) {
                int* c = &g_sync[256 + e];
                while (atomicAdd(c, 0) < NC_W1E) { }
                __threadfence();
            }
            __syncthreads();
        }
    } else {
        // ---------------- GEMM2 tile ----------------
        int u = bid - REGION1;                // u = tx + 8*ty + 256*e
        tx = u & 7; ty = (u >> 3) & 31; e = u >> 8;
        N = DD; K = HD;
        Az = hbuf + (size_t)e * BD * HD;
        Bz = w2h + (size_t)e * HD * DD;
        biz = b2 + (size_t)e * DD;
        if (tid == 0) {
            int* cw = &g_sync[264 + e];               // per-expert W2 gate
            while (atomicAdd(cw, 0) < NC_W2E) { }
            int* c = &g_sync[e * 32 + ty];            // 16 h producer tiles
            while (atomicAdd(c, 0) < 16) { }
            __threadfence();
        }
        __syncthreads();
    }
    const int m0 = ty * BM, n0 = tx * BN;

    const uint32_t sbase = (uint32_t)__cvta_generic_to_shared(smem);
    const uint32_t sA = sbase;
    const uint32_t sB = sbase + (uint32_t)(STAGES * A_STAGE * 2);

    const int lane = tid & 31;
    const int warp = tid >> 5;
    const int wm = (warp >> 2) * 64;
    const int wn = (warp & 3) * 32;
    const int lr = (lane & 7) + ((lane >> 3) & 1) * 8;
    const int lc = ((lane >> 4) & 1) * 8;

    auto load_stage = [&](int st, int kt) {
        const __half* Ag = Az + (size_t)m0 * K + (size_t)kt * BK;
        const __half* Bg = Bz + (size_t)kt * BK * N + n0;
        #pragma unroll
        for (int it = 0; it < 2; it++) {
            int c = tid + it * 256;
            int ar = c >> 2, ak = (c & 3) * 8;
            cp16(sA + (uint32_t)(st * A_STAGE + ar * ASTR + ak) * 2,
                 Ag + (size_t)ar * K + ak);
            int br = c >> 4, bn = (c & 15) * 8;
            cp16(sB + (uint32_t)(st * B_STAGE + br * BSTR + bn) * 2,
                 Bg + (size_t)br * N + bn);
        }
    };

    float acc[4][4][4] = {};

    auto compute_stage = [&](int st) {
        #pragma unroll
        for (int ks = 0; ks < BK / 16; ks++) {
            uint32_t af[4][4];
            #pragma unroll
            for (int mt = 0; mt < 4; mt++)
                ldsm4(af[mt], sA + (uint32_t)(st * A_STAGE + (wm + mt*16 + lr) * ASTR + ks*16 + lc) * 2);
            uint32_t bf[2][4];
            #pragma unroll
            for (int nt = 0; nt < 2; nt++)
                ldsm4t(bf[nt], sB + (uint32_t)(st * B_STAGE + (ks*16 + lr) * BSTR + wn + nt*16 + lc) * 2);
            #pragma unroll
            for (int mt = 0; mt < 4; mt++)
                #pragma unroll
                for (int n8 = 0; n8 < 4; n8++)
                    mma16816(acc[mt][n8], af[mt],
                             bf[n8 >> 1][(n8 & 1) * 2], bf[n8 >> 1][(n8 & 1) * 2 + 1]);
        }
    };

    const int KT = K / BK;
    load_stage(0, 0); cp_commit();
    load_stage(1, 1); cp_commit();
    load_stage(2, 2); cp_commit();
    load_stage(3, 3); cp_commit();
    cp_wait<3>();
    __syncthreads();

    int buf = 0, ldb = 4;
    for (int kt = 0; kt < KT; kt++) {
        if (kt + 4 < KT) load_stage(ldb, kt + 4);
        cp_commit();
        compute_stage(buf);
        cp_wait<3>();
        __syncthreads();
        buf = (buf + 1 == STAGES) ? 0 : buf + 1;
        ldb = (ldb + 1 == STAGES) ? 0 : ldb + 1;
    }

    // Epilogue
    const int g = lane >> 2, t4 = lane & 3;
    if (g1) {
        __half* O = hbuf + (size_t)e * BD * HD;
        #pragma unroll
        for (int mt = 0; mt < 4; mt++) {
            int r0 = m0 + wm + mt * 16 + g;
            #pragma unroll
            for (int n8 = 0; n8 < 4; n8++) {
                int col = n0 + wn + n8 * 8 + 2 * t4;
                float bb0 = biz[col], bb1 = biz[col + 1];
                float v00 = fmaxf(acc[mt][n8][0] + bb0, 0.f);
                float v01 = fmaxf(acc[mt][n8][1] + bb1, 0.f);
                float v10 = fmaxf(acc[mt][n8][2] + bb0, 0.f);
                float v11 = fmaxf(acc[mt][n8][3] + bb1, 0.f);
                *(__half2*)&O[(size_t)r0 * HD + col]       = __floats2half2_rn(v00, v01);
                *(__half2*)&O[(size_t)(r0 + 8) * HD + col] = __floats2half2_rn(v10, v11);
            }
        }
        __syncthreads();
        if (tid == 0) { __threadfence(); atomicAdd(&g_sync[e * 32 + ty], 1); }
    } else {
        float* O = out + (size_t)e * DD;                  // row stride ED*DD
        #pragma unroll
        for (int mt = 0; mt < 4; mt++) {
            int r0 = m0 + wm + mt * 16 + g;
            #pragma unroll
            for (int n8 = 0; n8 < 4; n8++) {
                int col = n0 + wn + n8 * 8 + 2 * t4;
                float bb0 = biz[col], bb1 = biz[col + 1];
                float2 lo = make_float2(acc[mt][n8][0] + bb0, acc[mt][n8][1] + bb1);
                float2 hi = make_float2(acc[mt][n8][2] + bb0, acc[mt][n8][3] + bb1);
                *(float2*)&O[(size_t)r0 * (ED * DD) + col]       = lo;
                *(float2*)&O[(size_t)(r0 + 8) * (ED * DD) + col] = hi;
            }
        }
    }
}

// ---------------------------------------------------------------- launch
extern "C" void kernel_launch(void* const* d_in, const int* in_sizes, int n_in,
                              void* d_out, int out_size) {
    const float* x  = (const float*)d_in[0];   // [B, D]
    const float* W1 = (const float*)d_in[1];   // [E, D, H]
    const float* b1 = (const float*)d_in[2];   // [E, H]
    const float* W2 = (const float*)d_in[3];   // [E, H, D]
    const float* b2 = (const float*)d_in[4];   // [E, D]
    float* out = (float*)d_out;                // [B, E, D]

    __half *xh, *w1h, *w2h, *hbuf;
    int* syncp;
    cudaGetSymbolAddress((void**)&xh,   g_xh);
    cudaGetSymbolAddress((void**)&w1h,  g_w1h);
    cudaGetSymbolAddress((void**)&w2h,  g_w2h);
    cudaGetSymbolAddress((void**)&hbuf, g_h);
    cudaGetSymbolAddress((void**)&syncp, g_sync);

    cudaFuncSetAttribute(fused_kernel, cudaFuncAttributeMaxDynamicSharedMemorySize, (int)SMEM_BYTES);

    int sm = 148;
    cudaDeviceGetAttribute(&sm, cudaDevAttrMultiProcessorCount, 0);

    // Reset dependency counters (graph-capturable memset node)
    cudaMemsetAsync(syncp, 0, sizeof(int) * SYNC_N);

    // Pre-convert at full-chip bandwidth: x + W1 expert 0 (~48 MB)
    cvt_pre<<<sm * 8, 256>>>(x, W1, xh, w1h);

    // Fused: W1[1..7] cvt + W2 cvt (per-expert) + GEMM1 + GEMM2
    fused_kernel<<<FUSED_GRID, 256, SMEM_BYTES>>>(xh, w1h, hbuf, W1, W2,
                                                  w1h, w2h, b1, b2, out);
}

// round 17
// speedup vs baseline: 1.0255x; 1.0255x over previous
#include <cuda_runtime.h>
#include <cuda_fp16.h>
#include <cstdint>

// Problem shape (fixed by the reference)
constexpr int BD = 4096;   // batch rows
constexpr int DD = 1024;   // model dim
constexpr int HD = 2048;   // hidden dim
constexpr int ED = 8;      // experts

// GEMM tiling: 128x128x32 CTA tile, 64x32 warp tile, 8 warps, 2 CTAs/SM.
// 5-stage cp.async ring, prefetch distance 4, wait_group<3>. (plateau-optimal)
constexpr int BM = 128, BN = 128, BK = 32;
constexpr int STAGES = 5;
constexpr int ASTR = BK + 8;              // 40 halves/row
constexpr int BSTR = BN + 8;              // 136 halves/row
constexpr int A_STAGE = BM * ASTR;        // 5120 halves
constexpr int B_STAGE = BK * BSTR;        // 4352 halves
constexpr size_t SMEM_BYTES = (size_t)STAGES * (A_STAGE + B_STAGE) * sizeof(__half); // 94720

// Convert ranges in float8 (32B) units
constexpr int N8_X    = (BD * DD) / 8;         // 524288
constexpr int N8_W1E  = (DD * HD) / 8;         // 262144 per expert
constexpr int N8_W2   = (ED * HD * DD) / 8;    // 2097152
constexpr int NC_W2   = 512;                   // W2 convert CTAs total
constexpr int N8_PER_W2CVT = N8_W2 / NC_W2;    // 4096
constexpr int NC_W1E  = 64;                    // W1 convert CTAs per expert (e>0)
constexpr int N8_PER_W1CVT = N8_W1E / NC_W1E;  // 4096

// Fused-kernel block layout.
// Per-expert block: [e>0: 64 W1-cvt] + 64 groups of 9 (1 W2-cvt + 8 GEMM1) = 576
constexpr int EBLK0 = 576;                     // expert 0 block
constexpr int EBLKN = NC_W1E + 576;            // experts 1..7 block (640)
constexpr int REGION1 = EBLK0 + 7 * EBLKN;     // 5056
constexpr int NT2 = (DD / BN) * (BD / BM) * ED; // 2048 GEMM2 tiles
constexpr int FUSED_GRID = REGION1 + NT2;      // 7104

// Scratch (allocation-free: __device__ globals)
__device__ __align__(256) __half g_xh [(size_t)BD * DD];
__device__ __align__(256) __half g_w1h[(size_t)ED * DD * HD];
__device__ __align__(256) __half g_w2h[(size_t)ED * HD * DD];
__device__ __align__(256) __half g_h  [(size_t)ED * BD * HD];

// Sync: [0]=W2 cvt count, [1+e*32+ty]=h row-block counters, [257+e]=W1 cvt count
__device__ int g_sync[1 + ED * 32 + ED];

// ---------------------------------------------------------------- convert helpers
__device__ __forceinline__ void cvt8(const float4* s, uint4* d, int j) {
    float4 v0 = s[2 * j];
    float4 v1 = s[2 * j + 1];
    __half2 h0 = __floats2half2_rn(v0.x, v0.y);
    __half2 h1 = __floats2half2_rn(v0.z, v0.w);
    __half2 h2 = __floats2half2_rn(v1.x, v1.y);
    __half2 h3 = __floats2half2_rn(v1.z, v1.w);
    uint4 o;
    o.x = *reinterpret_cast<uint32_t*>(&h0);
    o.y = *reinterpret_cast<uint32_t*>(&h1);
    o.z = *reinterpret_cast<uint32_t*>(&h2);
    o.w = *reinterpret_cast<uint32_t*>(&h3);
    d[j] = o;
}

// Pre-kernel: convert x + W1 expert 0 only (needed at fused-kernel start)
constexpr int N8_PRE = N8_X + N8_W1E;
__global__ void cvt_pre(const float* __restrict__ x, const float* __restrict__ W1,
                        __half* __restrict__ xh, __half* __restrict__ w1h) {
    for (int i = blockIdx.x * blockDim.x + threadIdx.x; i < N8_PRE;
         i += gridDim.x * blockDim.x) {
        if (i < N8_X) cvt8((const float4*)x, (uint4*)xh, i);
        else          cvt8((const float4*)W1, (uint4*)w1h, i - N8_X);
    }
}

// ---------------------------------------------------------------- PTX utils
__device__ __forceinline__ void cp16(uint32_t saddr, const void* g) {
    asm volatile("cp.async.cg.shared.global [%0], [%1], 16;\n" :: "r"(saddr), "l"(g));
}
__device__ __forceinline__ void cp_commit() { asm volatile("cp.async.commit_group;\n"); }
template<int N> __device__ __forceinline__ void cp_wait() {
    asm volatile("cp.async.wait_group %0;\n" :: "n"(N));
}
__device__ __forceinline__ void ldsm4(uint32_t* r, uint32_t saddr) {
    asm volatile("ldmatrix.sync.aligned.m8n8.x4.shared.b16 {%0,%1,%2,%3}, [%4];\n"
        : "=r"(r[0]), "=r"(r[1]), "=r"(r[2]), "=r"(r[3]) : "r"(saddr));
}
__device__ __forceinline__ void ldsm4t(uint32_t* r, uint32_t saddr) {
    asm volatile("ldmatrix.sync.aligned.m8n8.x4.trans.shared.b16 {%0,%1,%2,%3}, [%4];\n"
        : "=r"(r[0]), "=r"(r[1]), "=r"(r[2]), "=r"(r[3]) : "r"(saddr));
}
__device__ __forceinline__ void mma16816(float* c, const uint32_t* a, uint32_t b0, uint32_t b1) {
    asm volatile("mma.sync.aligned.m16n8k16.row.col.f32.f16.f16.f32 "
        "{%0,%1,%2,%3}, {%4,%5,%6,%7}, {%8,%9}, {%0,%1,%2,%3};\n"
        : "+f"(c[0]), "+f"(c[1]), "+f"(c[2]), "+f"(c[3])
        : "r"(a[0]), "r"(a[1]), "r"(a[2]), "r"(a[3]), "r"(b0), "r"(b1));
}

// ---------------------------------------------------------------- fused kernel
__global__ __launch_bounds__(256, 2)
void fused_kernel(const __half* __restrict__ xh, const __half* __restrict__ w1h,
                  __half* __restrict__ hbuf,
                  const float* __restrict__ W1, const float* __restrict__ W2,
                  __half* __restrict__ w1hw, __half* __restrict__ w2h,
                  const float* __restrict__ b1, const float* __restrict__ b2,
                  float* __restrict__ out)
{
    extern __shared__ __align__(16) __half smem[];
    const int bid = blockIdx.x;
    const int tid = threadIdx.x;

    bool g1 = false;
    int e, ty, tx, N, K;
    const __half *Az, *Bz;
    const float* biz;

    if (bid < REGION1) {
        // Decode expert block
        int eb, r;
        if (bid < EBLK0) { eb = 0; r = bid; }
        else { int b = bid - EBLK0; eb = 1 + b / EBLKN; r = b % EBLKN; }

        if (eb > 0 && r < NC_W1E) {
            // ---------------- W1[eb] convert CTA ----------------
            const float4* s = (const float4*)W1;
            uint4* d = (uint4*)w1hw;
            int base = eb * N8_W1E + r * N8_PER_W1CVT;
            #pragma unroll 4
            for (int i = tid; i < N8_PER_W1CVT; i += 256)
                cvt8(s, d, base + i);
            __syncthreads();
            if (tid == 0) { __threadfence(); atomicAdd(&g_sync[257 + eb], 1); }
            return;
        }
        int r2 = (eb > 0) ? r - NC_W1E : r;   // 0..575
        const int grp = r2 / 9;
        const int sub = r2 - grp * 9;
        if (sub == 0) {
            // ---------------- W2 convert CTA (interleaved) ----------------
            const float4* s = (const float4*)W2;
            uint4* d = (uint4*)w2h;
            int base = (eb * 64 + grp) * N8_PER_W2CVT;
            #pragma unroll 4
            for (int i = tid; i < N8_PER_W2CVT; i += 256)
                cvt8(s, d, base + i);
            __syncthreads();
            if (tid == 0) { __threadfence(); atomicAdd(&g_sync[0], 1); }
            return;
        }
        // ---------------- GEMM1 tile ----------------
        g1 = true;
        e = eb;
        int t = grp * 8 + (sub - 1);          // 0..511 within expert: t = tx + 16*ty
        tx = t & 15; ty = t >> 4;
        N = HD; K = DD;
        Az = xh;
        Bz = w1h + (size_t)e * DD * HD;
        biz = b1 + (size_t)e * HD;
        if (e > 0) {
            if (tid == 0) {
                int* c = &g_sync[257 + e];
                while (atomicAdd(c, 0) < NC_W1E) { }
                __threadfence();
            }
            __syncthreads();
        }
    } else {
        // ---------------- GEMM2 tile ----------------
        int u = bid - REGION1;                // u = tx + 8*ty + 256*e
        tx = u & 7; ty = (u >> 3) & 31; e = u >> 8;
        N = DD; K = HD;
        Az = hbuf + (size_t)e * BD * HD;
        Bz = w2h + (size_t)e * HD * DD;
        biz = b2 + (size_t)e * DD;
        if (tid == 0) {
            while (atomicAdd(&g_sync[0], 0) < NC_W2) { }
            int* c = &g_sync[1 + e * 32 + ty];
            while (atomicAdd(c, 0) < 16) { }
            __threadfence();
        }
        __syncthreads();
    }
    const int m0 = ty * BM, n0 = tx * BN;

    const uint32_t sbase = (uint32_t)__cvta_generic_to_shared(smem);
    const uint32_t sA = sbase;
    const uint32_t sB = sbase + (uint32_t)(STAGES * A_STAGE * 2);

    const int lane = tid & 31;
    const int warp = tid >> 5;
    const int wm = (warp >> 2) * 64;
    const int wn = (warp & 3) * 32;
    const int lr = (lane & 7) + ((lane >> 3) & 1) * 8;
    const int lc = ((lane >> 4) & 1) * 8;

    auto load_stage = [&](int st, int kt) {
        const __half* Ag = Az + (size_t)m0 * K + (size_t)kt * BK;
        const __half* Bg = Bz + (size_t)kt * BK * N + n0;
        #pragma unroll
        for (int it = 0; it < 2; it++) {
            int c = tid + it * 256;
            int ar = c >> 2, ak = (c & 3) * 8;
            cp16(sA + (uint32_t)(st * A_STAGE + ar * ASTR + ak) * 2,
                 Ag + (size_t)ar * K + ak);
            int br = c >> 4, bn = (c & 15) * 8;
            cp16(sB + (uint32_t)(st * B_STAGE + br * BSTR + bn) * 2,
                 Bg + (size_t)br * N + bn);
        }
    };

    float acc[4][4][4] = {};

    auto compute_stage = [&](int st) {
        #pragma unroll
        for (int ks = 0; ks < BK / 16; ks++) {
            uint32_t af[4][4];
            #pragma unroll
            for (int mt = 0; mt < 4; mt++)
                ldsm4(af[mt], sA + (uint32_t)(st * A_STAGE + (wm + mt*16 + lr) * ASTR + ks*16 + lc) * 2);
            uint32_t bf[2][4];
            #pragma unroll
            for (int nt = 0; nt < 2; nt++)
                ldsm4t(bf[nt], sB + (uint32_t)(st * B_STAGE + (ks*16 + lr) * BSTR + wn + nt*16 + lc) * 2);
            #pragma unroll
            for (int mt = 0; mt < 4; mt++)
                #pragma unroll
                for (int n8 = 0; n8 < 4; n8++)
                    mma16816(acc[mt][n8], af[mt],
                             bf[n8 >> 1][(n8 & 1) * 2], bf[n8 >> 1][(n8 & 1) * 2 + 1]);
        }
    };

    const int KT = K / BK;
    load_stage(0, 0); cp_commit();
    load_stage(1, 1); cp_commit();
    load_stage(2, 2); cp_commit();
    load_stage(3, 3); cp_commit();
    cp_wait<3>();
    __syncthreads();

    int buf = 0, ldb = 4;
    for (int kt = 0; kt < KT; kt++) {
        if (kt + 4 < KT) load_stage(ldb, kt + 4);
        cp_commit();
        compute_stage(buf);
        cp_wait<3>();
        __syncthreads();
        buf = (buf + 1 == STAGES) ? 0 : buf + 1;
        ldb = (ldb + 1 == STAGES) ? 0 : ldb + 1;
    }

    // Epilogue
    const int g = lane >> 2, t4 = lane & 3;
    if (g1) {
        __half* O = hbuf + (size_t)e * BD * HD;
        #pragma unroll
        for (int mt = 0; mt < 4; mt++) {
            int r0 = m0 + wm + mt * 16 + g;
            #pragma unroll
            for (int n8 = 0; n8 < 4; n8++) {
                int col = n0 + wn + n8 * 8 + 2 * t4;
                float bb0 = biz[col], bb1 = biz[col + 1];
                float v00 = fmaxf(acc[mt][n8][0] + bb0, 0.f);
                float v01 = fmaxf(acc[mt][n8][1] + bb1, 0.f);
                float v10 = fmaxf(acc[mt][n8][2] + bb0, 0.f);
                float v11 = fmaxf(acc[mt][n8][3] + bb1, 0.f);
                *(__half2*)&O[(size_t)r0 * HD + col]       = __floats2half2_rn(v00, v01);
                *(__half2*)&O[(size_t)(r0 + 8) * HD + col] = __floats2half2_rn(v10, v11);
            }
        }
        __syncthreads();
        if (tid == 0) { __threadfence(); atomicAdd(&g_sync[1 + e * 32 + ty], 1); }
    } else {
        float* O = out + (size_t)e * DD;                  // row stride ED*DD
        #pragma unroll
        for (int mt = 0; mt < 4; mt++) {
            int r0 = m0 + wm + mt * 16 + g;
            #pragma unroll
            for (int n8 = 0; n8 < 4; n8++) {
                int col = n0 + wn + n8 * 8 + 2 * t4;
                float bb0 = biz[col], bb1 = biz[col + 1];
                float2 lo = make_float2(acc[mt][n8][0] + bb0, acc[mt][n8][1] + bb1);
                float2 hi = make_float2(acc[mt][n8][2] + bb0, acc[mt][n8][3] + bb1);
                *(float2*)&O[(size_t)r0 * (ED * DD) + col]       = lo;
                *(float2*)&O[(size_t)(r0 + 8) * (ED * DD) + col] = hi;
            }
        }
    }
}

// ---------------------------------------------------------------- launch
extern "C" void kernel_launch(void* const* d_in, const int* in_sizes, int n_in,
                              void* d_out, int out_size) {
    const float* x  = (const float*)d_in[0];   // [B, D]
    const float* W1 = (const float*)d_in[1];   // [E, D, H]
    const float* b1 = (const float*)d_in[2];   // [E, H]
    const float* W2 = (const float*)d_in[3];   // [E, H, D]
    const float* b2 = (const float*)d_in[4];   // [E, D]
    float* out = (float*)d_out;                // [B, E, D]

    __half *xh, *w1h, *w2h, *hbuf;
    int* syncp;
    cudaGetSymbolAddress((void**)&xh,   g_xh);
    cudaGetSymbolAddress((void**)&w1h,  g_w1h);
    cudaGetSymbolAddress((void**)&w2h,  g_w2h);
    cudaGetSymbolAddress((void**)&hbuf, g_h);
    cudaGetSymbolAddress((void**)&syncp, g_sync);

    cudaFuncSetAttribute(fused_kernel, cudaFuncAttributeMaxDynamicSharedMemorySize, (int)SMEM_BYTES);

    int sm = 148;
    cudaDeviceGetAttribute(&sm, cudaDevAttrMultiProcessorCount, 0);

    // Reset dependency counters (graph-capturable memset node)
    cudaMemsetAsync(syncp, 0, sizeof(int) * (1 + ED * 32 + ED));

    // Pre-convert: x + W1 expert 0 only (~48 MB)
    cvt_pre<<<sm * 8, 256>>>(x, W1, xh, w1h);

    // Fused: W1[1..7] cvt + W2 cvt + GEMM1 + GEMM2 with intra-kernel dependencies
    fused_kernel<<<FUSED_GRID, 256, SMEM_BYTES>>>(xh, w1h, hbuf, W1, W2,
                                                  w1h, w2h, b1, b2, out);
}